// round 5
// baseline (speedup 1.0000x reference)
#include <cuda_runtime.h>

#define BB     8
#define NWAY   10
#define KSHOT  5
#define QN     500
#define DD     768
#define NQ     (BB * QN)        // 4000
#define NL     (NWAY + 1)       // 11
#define QPW    2                // queries per warp
#define BLKW   8                // warps per block
#define QPB    (QPW * BLKW)     // 16 queries per block
#define BPE    32               // blocks per episode (31 full + 1 partial)
#define NBLK   (BB * BPE)       // 256 blocks

__device__ float g_S[BB * NWAY * DD];
__device__ float g_ssq[BB * NWAY];

// ---------------------------------------------------------------------------
// Kernel 1: prototypes + squared norms. One block per (b,n).
// ---------------------------------------------------------------------------
__global__ void __launch_bounds__(128) proto_kernel(const float* __restrict__ sup) {
    int bn = blockIdx.x;            // 0..79
    int t  = threadIdx.x;           // 0..127
    const float* base = sup + (size_t)bn * KSHOT * DD;
    float part = 0.0f;
#pragma unroll
    for (int j = 0; j < DD / 128; j++) {
        int d = t + j * 128;
        float s = 0.0f;
#pragma unroll
        for (int k = 0; k < KSHOT; k++) s += base[k * DD + d];
        s *= 0.2f;
        g_S[bn * DD + d] = s;
        part += s * s;
    }
#pragma unroll
    for (int off = 16; off; off >>= 1)
        part += __shfl_xor_sync(0xffffffffu, part, off);
    __shared__ float red[4];
    if ((t & 31) == 0) red[t >> 5] = part;
    __syncthreads();
    if (t == 0) g_ssq[bn] = red[0] + red[1] + red[2] + red[3];
}

// ---------------------------------------------------------------------------
// Kernel 2: S staged in shared memory (one episode per block), queries
// hoisted into a register burst that overlaps the cooperative S fill.
// Mainloop touches only registers + smem -> no L2-latency chain.
// ---------------------------------------------------------------------------
__global__ void __launch_bounds__(256, 2) main_kernel(const float* __restrict__ qin,
                                                      float* __restrict__ out,
                                                      int out_size) {
    __shared__ float4 sS[NWAY * DD / 4];    // 30 KB

    int tid   = threadIdx.x;
    int lane  = tid & 31;
    int wwarp = tid >> 5;                   // 0..7
    int b     = blockIdx.x >> 5;            // episode (BPE = 32)
    int blk   = blockIdx.x & 31;            // block within episode

    int qin_ep  = blk * QPB + wwarp * QPW;  // query offset within episode
    bool active = (qin_ep < QN);            // last block: only warps 0-1

    // ssq for this episode (tiny load, issued early)
    float ssq_r = (lane < NWAY) ? g_ssq[b * NWAY + lane] : 0.0f;

    // ---- query register burst (before the S fill so DRAM latency overlaps) --
    float4 q[QPW][6];
    if (active) {
        const float4* __restrict__ qv =
            (const float4*)(qin + ((size_t)b * QN + qin_ep) * DD);
#pragma unroll
        for (int qi = 0; qi < QPW; qi++)
#pragma unroll
            for (int j = 0; j < 6; j++)
                q[qi][j] = qv[qi * (DD / 4) + lane + 32 * j];
    }

    // ---- cooperative S fill: 1920 float4, 256 threads, all independent ----
    {
        const float4* __restrict__ gs = (const float4*)(g_S + (size_t)b * NWAY * DD);
#pragma unroll
        for (int i = 0; i < (NWAY * DD / 4) / 256; i++)       // 7 full rounds
            sS[tid + i * 256] = gs[tid + i * 256];
        int r = tid + ((NWAY * DD / 4) / 256) * 256;          // remainder 128
        if (r < NWAY * DD / 4) sS[r] = gs[r];
    }
    __syncthreads();
    if (!active) return;

    float dot[QPW][NWAY];
    float qsq[QPW];
#pragma unroll
    for (int qi = 0; qi < QPW; qi++) {
        qsq[qi] = 0.0f;
#pragma unroll
        for (int n = 0; n < NWAY; n++) dot[qi][n] = 0.0f;
    }

#pragma unroll
    for (int qi = 0; qi < QPW; qi++)
#pragma unroll
        for (int j = 0; j < 6; j++)
            qsq[qi] += q[qi][j].x * q[qi][j].x + q[qi][j].y * q[qi][j].y
                     + q[qi][j].z * q[qi][j].z + q[qi][j].w * q[qi][j].w;

    // ---- mainloop: S from smem (LDS.128, conflict-free), 8 FFMA per LDS ----
#pragma unroll
    for (int j = 0; j < 6; j++) {
#pragma unroll
        for (int n = 0; n < NWAY; n++) {
            float4 s = sS[n * (DD / 4) + lane + 32 * j];
#pragma unroll
            for (int qi = 0; qi < QPW; qi++) {
                dot[qi][n] += s.x * q[qi][j].x + s.y * q[qi][j].y
                            + s.z * q[qi][j].z + s.w * q[qi][j].w;
            }
        }
    }

    // ---- warp butterfly reduction of 22 accumulators ----
#pragma unroll
    for (int qi = 0; qi < QPW; qi++) {
#pragma unroll
        for (int n = 0; n < NWAY; n++) {
#pragma unroll
            for (int off = 16; off; off >>= 1)
                dot[qi][n] += __shfl_xor_sync(0xffffffffu, dot[qi][n], off);
        }
#pragma unroll
        for (int off = 16; off; off >>= 1)
            qsq[qi] += __shfl_xor_sync(0xffffffffu, qsq[qi], off);
    }

    // ---- epilogue: all lanes compute (converged shuffles); lanes 0..1 store
    int   qi = lane & (QPW - 1);
    int   qq = b * QN + qin_ep + qi;
    float myqsq = qsq[qi];

    float lg[NL];
    float mn =  3.4e38f, mx = -3.4e38f;
#pragma unroll
    for (int n = 0; n < NWAY; n++) {
        float sn = __shfl_sync(0xffffffffu, ssq_r, n);
        float v  = 2.0f * dot[qi][n] - sn - myqsq;
        lg[n] = v;
        mn = fminf(mn, v);
        mx = fmaxf(mx, v);
    }
    lg[NWAY] = mn - 1.0f;

    float ex[NL];
    float se = 0.0f;
#pragma unroll
    for (int i = 0; i < NL; i++) {
        ex[i] = __expf(lg[i] - mx);
        se += ex[i];
    }
    float inv = 1.0f / se;

    int   amax = 0;
    float bv   = lg[0];
#pragma unroll
    for (int i = 1; i < NL; i++)
        if (lg[i] > bv) { bv = lg[i]; amax = i; }

    if (lane < QPW) {
        // Output layout: fh[NQ*NL] | ph[NQ*NL] | yh_top[NQ] | ph_top[NQ]
        float* fh = out + (size_t)qq * NL;
#pragma unroll
        for (int i = 0; i < NL; i++) fh[i] = lg[i];

        if (out_size >= 2 * NQ * NL) {
            float* ph = out + (size_t)NQ * NL + (size_t)qq * NL;
#pragma unroll
            for (int i = 0; i < NL; i++) ph[i] = ex[i] * inv;
        }
        if (out_size >= 2 * NQ * NL + NQ)
            out[2 * NQ * NL + qq] = (float)amax;
        if (out_size >= 2 * NQ * NL + 2 * NQ)
            out[2 * NQ * NL + NQ + qq] = ex[amax] * inv;
    }
}

extern "C" void kernel_launch(void* const* d_in, const int* in_sizes, int n_in,
                              void* d_out, int out_size) {
    const float* support = (const float*)d_in[0];
    const float* query   = (const float*)d_in[1];
    float* out = (float*)d_out;

    proto_kernel<<<BB * NWAY, 128>>>(support);
    main_kernel<<<NBLK, 256>>>(query, out, out_size);
}

// round 6
// speedup vs baseline: 1.0077x; 1.0077x over previous
#include <cuda_runtime.h>
#include <cstdint>

#define BB     8
#define NWAY   10
#define KSHOT  5
#define QN     500
#define DD     768
#define NQ     (BB * QN)        // 4000
#define NL     (NWAY + 1)       // 11
#define QPW    2                // queries per warp
#define BLKW   8                // warps per block
#define QPB    (QPW * BLKW)     // 16 queries per block
#define BPE    32               // blocks per episode
#define NBLK   (BB * BPE)       // 256 blocks
#define SQ4    (DD / 4)         // 192 float4 per row
#define S_BYTES    (NWAY * DD * 4)   // 30720
#define QROW_BYTES (DD * 4)          // 3072

__device__ float g_S[BB * NWAY * DD];
__device__ float g_ssq[BB * NWAY];

// ---------------------------------------------------------------------------
// PTX helpers
// ---------------------------------------------------------------------------
__device__ __forceinline__ uint32_t smem_u32(const void* p) {
    uint32_t a;
    asm("{ .reg .u64 t; cvta.to.shared.u64 t, %1; cvt.u32.u64 %0, t; }"
        : "=r"(a) : "l"(p));
    return a;
}
#define MBAR_INIT(addr, cnt) \
    asm volatile("mbarrier.init.shared.b64 [%0], %1;" :: "r"(addr), "r"(cnt) : "memory")
#define MBAR_EXPECT_TX(addr, tx) \
    asm volatile("mbarrier.arrive.expect_tx.shared.b64 _, [%0], %1;" :: "r"(addr), "r"(tx) : "memory")
#define BULK_G2S(dst, src, bytes, mbar) \
    asm volatile("cp.async.bulk.shared::cluster.global.mbarrier::complete_tx::bytes [%0], [%1], %2, [%3];" \
                 :: "r"(dst), "l"(src), "r"(bytes), "r"(mbar) : "memory")
#define FENCE_PROXY_ASYNC() \
    asm volatile("fence.proxy.async.shared::cta;" ::: "memory")

__device__ __forceinline__ void mbar_wait(uint32_t mbar, uint32_t parity) {
    uint32_t done;
    asm volatile(
        "{ .reg .pred p;\n"
        " mbarrier.try_wait.parity.acquire.cta.shared::cta.b64 p, [%1], %2;\n"
        " selp.b32 %0, 1, 0, p; }"
        : "=r"(done) : "r"(mbar), "r"(parity) : "memory");
    if (!done) {
        asm volatile(
            "{ .reg .pred P1;\n"
            "WL_%=:\n"
            " mbarrier.try_wait.parity.acquire.cta.shared::cta.b64 P1, [%0], %1, 0x989680;\n"
            " @P1 bra.uni WD_%=;\n"
            " bra.uni WL_%=;\n"
            "WD_%=: }"
            :: "r"(mbar), "r"(parity) : "memory");
    }
}

// ---------------------------------------------------------------------------
// Kernel 1: prototypes + squared norms. One block per (b,n).
// ---------------------------------------------------------------------------
__global__ void __launch_bounds__(128) proto_kernel(const float* __restrict__ sup) {
    int bn = blockIdx.x;            // 0..79
    int t  = threadIdx.x;           // 0..127
    const float* base = sup + (size_t)bn * KSHOT * DD;
    float part = 0.0f;
#pragma unroll
    for (int j = 0; j < DD / 128; j++) {
        int d = t + j * 128;
        float s = 0.0f;
#pragma unroll
        for (int k = 0; k < KSHOT; k++) s += base[k * DD + d];
        s *= 0.2f;
        g_S[bn * DD + d] = s;
        part += s * s;
    }
#pragma unroll
    for (int off = 16; off; off >>= 1)
        part += __shfl_xor_sync(0xffffffffu, part, off);
    __shared__ float red[4];
    if ((t & 31) == 0) red[t >> 5] = part;
    __syncthreads();
    if (t == 0) g_ssq[bn] = red[0] + red[1] + red[2] + red[3];
}

// ---------------------------------------------------------------------------
// Kernel 2: queries + S delivered by cp.async.bulk (TMA path) into smem.
// Replaces ~96k scattered LDG sectors chip-wide with 512 bulk streams,
// escaping the per-SM outstanding-LDG cap that pinned HBM at ~1.2 TB/s.
// ---------------------------------------------------------------------------
struct SmemLayout {
    float4   sS[NWAY * SQ4];     // 30720 B
    float4   sQ[QPB * SQ4];      // 49152 B
    uint64_t mbar;
};

__global__ void __launch_bounds__(256, 2) main_kernel(const float* __restrict__ qin,
                                                      float* __restrict__ out,
                                                      int out_size) {
    extern __shared__ char smem_raw[];
    SmemLayout* sm = reinterpret_cast<SmemLayout*>(smem_raw);

    int tid   = threadIdx.x;
    int lane  = tid & 31;
    int wwarp = tid >> 5;                   // 0..7
    int b     = blockIdx.x >> 5;            // episode
    int blk   = blockIdx.x & 31;            // block within episode

    int  qin_ep = blk * QPB + wwarp * QPW;  // query offset within episode
    bool active = (qin_ep < QN);

    uint32_t mbar = smem_u32(&sm->mbar);

    if (tid == 0) {
        MBAR_INIT(mbar, 1);
        FENCE_PROXY_ASYNC();
    }
    __syncthreads();

    if (tid == 0) {
        // Very last block would read past the query array: clamp to 4 rows.
        uint32_t rows = (blockIdx.x == NBLK - 1) ? (QN - 31 * QPB) : QPB;
        uint32_t qbytes = rows * QROW_BYTES;
        MBAR_EXPECT_TX(mbar, S_BYTES + qbytes);
        const void* gs = (const void*)(g_S + (size_t)b * NWAY * DD);
        const void* gq = (const void*)(qin + ((size_t)b * QN + (size_t)blk * QPB) * DD);
        BULK_G2S(smem_u32(sm->sS), gs, S_BYTES, mbar);
        BULK_G2S(smem_u32(sm->sQ), gq, qbytes, mbar);
    }

    // ssq for this episode (tiny; L2-hit)
    float ssq_r = (lane < NWAY) ? g_ssq[b * NWAY + lane] : 0.0f;

    mbar_wait(mbar, 0);
    if (!active) return;

    // ---- lift this warp's 2 query rows smem -> regs (LDS.128, 29cy) ----
    float4 q[QPW][6];
#pragma unroll
    for (int qi = 0; qi < QPW; qi++)
#pragma unroll
        for (int j = 0; j < 6; j++)
            q[qi][j] = sm->sQ[(wwarp * QPW + qi) * SQ4 + lane + 32 * j];

    float dot[QPW][NWAY];
    float qsq[QPW];
#pragma unroll
    for (int qi = 0; qi < QPW; qi++) {
        qsq[qi] = 0.0f;
#pragma unroll
        for (int n = 0; n < NWAY; n++) dot[qi][n] = 0.0f;
    }

#pragma unroll
    for (int qi = 0; qi < QPW; qi++)
#pragma unroll
        for (int j = 0; j < 6; j++)
            qsq[qi] += q[qi][j].x * q[qi][j].x + q[qi][j].y * q[qi][j].y
                     + q[qi][j].z * q[qi][j].z + q[qi][j].w * q[qi][j].w;

    // ---- mainloop: S from smem, 8 FFMA per LDS.128 ----
#pragma unroll
    for (int j = 0; j < 6; j++) {
#pragma unroll
        for (int n = 0; n < NWAY; n++) {
            float4 s = sm->sS[n * SQ4 + lane + 32 * j];
#pragma unroll
            for (int qi = 0; qi < QPW; qi++) {
                dot[qi][n] += s.x * q[qi][j].x + s.y * q[qi][j].y
                            + s.z * q[qi][j].z + s.w * q[qi][j].w;
            }
        }
    }

    // ---- warp butterfly reduction of 22 accumulators ----
#pragma unroll
    for (int qi = 0; qi < QPW; qi++) {
#pragma unroll
        for (int n = 0; n < NWAY; n++) {
#pragma unroll
            for (int off = 16; off; off >>= 1)
                dot[qi][n] += __shfl_xor_sync(0xffffffffu, dot[qi][n], off);
        }
#pragma unroll
        for (int off = 16; off; off >>= 1)
            qsq[qi] += __shfl_xor_sync(0xffffffffu, qsq[qi], off);
    }

    // ---- epilogue: converged shuffles; lanes 0..1 store ----
    int   qi = lane & (QPW - 1);
    int   qq = b * QN + qin_ep + qi;
    float myqsq = qsq[qi];

    float lg[NL];
    float mn =  3.4e38f, mx = -3.4e38f;
#pragma unroll
    for (int n = 0; n < NWAY; n++) {
        float sn = __shfl_sync(0xffffffffu, ssq_r, n);
        float v  = 2.0f * dot[qi][n] - sn - myqsq;
        lg[n] = v;
        mn = fminf(mn, v);
        mx = fmaxf(mx, v);
    }
    lg[NWAY] = mn - 1.0f;

    float ex[NL];
    float se = 0.0f;
#pragma unroll
    for (int i = 0; i < NL; i++) {
        ex[i] = __expf(lg[i] - mx);
        se += ex[i];
    }
    float inv = 1.0f / se;

    int   amax = 0;
    float bv   = lg[0];
#pragma unroll
    for (int i = 1; i < NL; i++)
        if (lg[i] > bv) { bv = lg[i]; amax = i; }

    if (lane < QPW) {
        // Output layout: fh[NQ*NL] | ph[NQ*NL] | yh_top[NQ] | ph_top[NQ]
        float* fh = out + (size_t)qq * NL;
#pragma unroll
        for (int i = 0; i < NL; i++) fh[i] = lg[i];

        if (out_size >= 2 * NQ * NL) {
            float* ph = out + (size_t)NQ * NL + (size_t)qq * NL;
#pragma unroll
            for (int i = 0; i < NL; i++) ph[i] = ex[i] * inv;
        }
        if (out_size >= 2 * NQ * NL + NQ)
            out[2 * NQ * NL + qq] = (float)amax;
        if (out_size >= 2 * NQ * NL + 2 * NQ)
            out[2 * NQ * NL + NQ + qq] = ex[amax] * inv;
    }
}

extern "C" void kernel_launch(void* const* d_in, const int* in_sizes, int n_in,
                              void* d_out, int out_size) {
    const float* support = (const float*)d_in[0];
    const float* query   = (const float*)d_in[1];
    float* out = (float*)d_out;

    static_assert(sizeof(SmemLayout) < 100 * 1024, "smem budget");
    cudaFuncSetAttribute(main_kernel,
                         cudaFuncAttributeMaxDynamicSharedMemorySize,
                         (int)sizeof(SmemLayout));

    proto_kernel<<<BB * NWAY, 128>>>(support);
    main_kernel<<<NBLK, 256, sizeof(SmemLayout)>>>(query, out, out_size);
}